// round 7
// baseline (speedup 1.0000x reference)
#include <cuda_runtime.h>
#include <cuda_bf16.h>
#include <cstdint>

// ---------------------------------------------------------------------------
// Problem constants
// ---------------------------------------------------------------------------
#define BATCH 8
#define CIN   32
#define HH    96
#define WW    96
#define OCN   64
#define OHW   96
#define SSZ   (OHW*OHW)      // 9216
#define KK    (CIN*3*3)      // 288

#define TILE_H 16
#define TILE_W 16
#define PATCH_H 18
#define PATCH_W 18
#define NPIX    (PATCH_H*PATCH_W)    // 324

// Dynamic smem layout (bytes)
#define SM_WH     0                   // Wh: 9*64 rows x 128B = 73728
#define SM_WL     73728               // Wl: 73728
#define SM_PH     147456              // patch hi: 324 rows x 128B = 41472
#define SM_PL     188928              // patch lo: 41472
#define SM_BIAS   230400              // 64 floats
#define SM_TOTAL  230656

// Preprocessed weights: [2 (hi/lo)][9 tap][64 oc][64 k] bf16, k-chunk aligned
__device__ __align__(16) __nv_bfloat16 g_W[2*9*64*64];
__device__ float g_bias[OCN];
// Precomputed NHWC bf16 images: [B][H][W][64ch], ch = [u0(cin)|u1(cin)]
__device__ __align__(16) __nv_bfloat16 g_IMG_H[BATCH*HH*WW*64];
__device__ __align__(16) __nv_bfloat16 g_IMG_L[BATCH*HH*WW*64];

// ---------------------------------------------------------------------------
// Prep 1: slopes -> bf16 hi/lo weight tiles + bias.  grid(64), block(288)
// ---------------------------------------------------------------------------
__global__ void prep_w_kernel(const float* __restrict__ pos,
                              const float* __restrict__ val) {
    int oc = blockIdx.x;
    int k  = threadIdx.x;              // cin*9 + tap
    __shared__ float red[KK];

    const float* p = pos + ((size_t)(oc*KK + k))*3;
    const float* v = val + ((size_t)(oc*KK + k))*3;
    float p0 = p[0], p1 = p[1], p2 = p[2];
    float v0 = v[0], v1 = v[1], v2 = v[2];
    float dp0 = p1 - p0, dp1 = p2 - p1;
    float s0 = (dp0 > 0.f) ? (v1 - v0) / dp0 : 0.f;
    float s1 = (dp1 > 0.f) ? (v2 - v1) / dp1 : 0.f;

    int cin = k / 9;
    int tap = k - cin*9;

    __nv_bfloat16 h0 = __float2bfloat16(s0);
    __nv_bfloat16 l0 = __float2bfloat16(s0 - __bfloat162float(h0));
    __nv_bfloat16 h1 = __float2bfloat16(s1);
    __nv_bfloat16 l1 = __float2bfloat16(s1 - __bfloat162float(h1));

    size_t rb = ((size_t)tap*64 + oc)*64;
    g_W[rb + cin]              = h0;
    g_W[rb + 32 + cin]         = h1;
    g_W[36864 + rb + cin]      = l0;
    g_W[36864 + rb + 32 + cin] = l1;

    red[k] = v0 - s0*p0 - s1*p1;
    __syncthreads();
    if (k == 0) {
        float s = 0.f;
        for (int i = 0; i < KK; i++) s += red[i];
        g_bias[oc] = s;
    }
}

// ---------------------------------------------------------------------------
// Prep 2: x -> NHWC bf16 hi/lo clipped images.  grid(768), block(256)
// ---------------------------------------------------------------------------
__global__ __launch_bounds__(256)
void prep_img_kernel(const float* __restrict__ x,
                     const float* __restrict__ pos) {
    __shared__ float f[CIN][WW];
    int bh = blockIdx.x;
    int b = bh / HH, h = bh - b*HH;
    int tid = threadIdx.x;

    float p0 = pos[0], p1 = pos[1], p2 = pos[2];

    const float* xr = x + ((size_t)b*CIN)*HH*WW + (size_t)h*WW;
    for (int idx = tid; idx < CIN*WW; idx += 256) {
        int c = idx / WW, w = idx - c*WW;
        f[c][w] = xr[(size_t)c*HH*WW + w];
    }
    __syncthreads();

    uint32_t* oh32 = (uint32_t*)g_IMG_H + ((size_t)(b*HH + h))*WW*32;
    uint32_t* ol32 = (uint32_t*)g_IMG_L + ((size_t)(b*HH + h))*WW*32;
    for (int idx = tid; idx < WW*32; idx += 256) {
        int w = idx >> 5, j = idx & 31;          // j = ch pair index
        int k0 = 2*j;
        int cin0 = k0 & 31, cin1 = (k0 + 1) & 31;
        float x0 = f[cin0][w], x1 = f[cin1][w];
        float u0 = (k0     < 32) ? fminf(fmaxf(x0, p0), p1)
                                 : fminf(fmaxf(x0, p1), p2);
        float u1 = (k0 + 1 < 32) ? fminf(fmaxf(x1, p0), p1)
                                 : fminf(fmaxf(x1, p1), p2);
        __nv_bfloat162 h2 = __floats2bfloat162_rn(u0, u1);
        float2 hf = __bfloat1622float2(h2);
        __nv_bfloat162 l2 = __floats2bfloat162_rn(u0 - hf.x, u1 - hf.y);
        oh32[idx] = reinterpret_cast<const uint32_t&>(h2);
        ol32[idx] = reinterpret_cast<const uint32_t&>(l2);
    }
}

// ---------------------------------------------------------------------------
// MMA / cp.async helpers (baseline sm_80+ PTX)
// ---------------------------------------------------------------------------
__device__ __forceinline__ void ldsm4(uint32_t& r0, uint32_t& r1,
                                      uint32_t& r2, uint32_t& r3,
                                      uint32_t addr) {
    asm volatile("ldmatrix.sync.aligned.m8n8.x4.shared.b16 {%0,%1,%2,%3}, [%4];"
                 : "=r"(r0), "=r"(r1), "=r"(r2), "=r"(r3) : "r"(addr));
}
__device__ __forceinline__ void mma_bf16(float* d,
                                         uint32_t a0, uint32_t a1,
                                         uint32_t a2, uint32_t a3,
                                         uint32_t b0, uint32_t b1) {
    asm volatile(
        "mma.sync.aligned.m16n8k16.row.col.f32.bf16.bf16.f32 "
        "{%0,%1,%2,%3}, {%4,%5,%6,%7}, {%8,%9}, {%0,%1,%2,%3};"
        : "+f"(d[0]), "+f"(d[1]), "+f"(d[2]), "+f"(d[3])
        : "r"(a0), "r"(a1), "r"(a2), "r"(a3), "r"(b0), "r"(b1));
}
__device__ __forceinline__ uint32_t smem_u32(const void* p) {
    uint32_t a;
    asm("{ .reg .u64 t; cvta.to.shared.u64 t, %1; cvt.u32.u64 %0, t; }"
        : "=r"(a) : "l"(p));
    return a;
}
__device__ __forceinline__ void cp_async16(uint32_t dst, const void* src,
                                           uint32_t src_size) {
    asm volatile("cp.async.cg.shared.global [%0], [%1], 16, %2;"
                 :: "r"(dst), "l"(src), "r"(src_size) : "memory");
}
__device__ __forceinline__ void cp_async_commit_wait0() {
    asm volatile("cp.async.commit_group;" ::: "memory");
    asm volatile("cp.async.wait_group 0;" ::: "memory");
}

// ---------------------------------------------------------------------------
// Main: grid(144) x 2 tiles each. Tile = 16oh x 16ow = 256 positions.
// 8 warps; warp w owns oh rows {2w, 2w+1} (2 MMA row-blocks, B frags reused).
// Patch staging = pure cp.async copy of precomputed bf16 images (swizzled).
// ---------------------------------------------------------------------------
__global__ __launch_bounds__(256, 1)
void pw_mma_kernel(float* __restrict__ out) {
    extern __shared__ char smem[];
    const uint32_t sb = smem_u32(smem);
    const int tid = threadIdx.x;
    const int l   = tid & 31;
    const int w   = tid >> 5;

    // ---- Stage all weights (hi+lo) into smem, XOR-swizzled 16B chunks ----
    {
        const uint4* gw = (const uint4*)g_W;
        for (int idx = tid; idx < 9216; idx += 256) {   // 1152 rows x 8 chunks
            int row = idx >> 3, kc = idx & 7;
            *(uint4*)(smem + row*128 + ((kc ^ (row & 7)) << 4)) = gw[idx];
        }
        if (tid < OCN)
            *(float*)(smem + SM_BIAS + tid*4) = g_bias[tid];
    }

    // lane constants (identical choreography to validated R6 kernel)
    const int rA     = l & 15;
    const int khalfA = l >> 4;
    const int ocb    = ((l >> 4) & 1)*8 + (l & 7);
    const int khalfB = (l >> 3) & 1;
    const int bsw    = l & 7;

    const char* imgH = (const char*)g_IMG_H;
    const char* imgL = (const char*)g_IMG_L;

    for (int t = 0; t < 2; t++) {
        int tile = blockIdx.x*2 + t;
        int bb   = tile / 36;
        int rem  = tile - bb*36;
        int oh0  = (rem / 6) * TILE_H;
        int ow0  = (rem - (rem/6)*6) * TILE_W;

        __syncthreads();   // weights staged (t=0) / prior tile's MMAs done

        // ---- Patch staging: cp.async, swizzled dst, OOB -> zero-fill ----
        for (int idx = tid; idx < 2*NPIX*8; idx += 256) {   // 5184 chunks
            int arr = idx >= NPIX*8;
            int e   = idx - arr*NPIX*8;
            int p   = e >> 3, c = e & 7;
            int ph  = p / PATCH_W;
            int pw  = p - ph*PATCH_W;
            int h   = oh0 - 1 + ph;
            int w2  = ow0 - 1 + pw;
            int inb = ((unsigned)h < HH) && ((unsigned)w2 < WW);
            int hc  = inb ? h : 0;
            int wc  = inb ? w2 : 0;
            const char* src = (arr ? imgL : imgH)
                + ((size_t)((bb*HH + hc)*WW + wc))*128 + c*16;
            uint32_t dst = sb + (arr ? SM_PL : SM_PH)
                + p*128 + ((c ^ (p & 7)) << 4);
            cp_async16(dst, src, inb ? 16u : 0u);
        }
        cp_async_commit_wait0();
        __syncthreads();

        // ---- 9-tap HMMA accumulation, 2 row-blocks per warp ----
        float acc[2][8][4];
#pragma unroll
        for (int r = 0; r < 2; r++)
#pragma unroll
            for (int nt = 0; nt < 8; nt++)
#pragma unroll
                for (int i = 0; i < 4; i++) acc[r][nt][i] = 0.f;

        for (int tap = 0; tap < 9; tap++) {
            int kh = tap / 3, kw = tap - (tap/3)*3;
            uint32_t boff = sb + (tap*64 + ocb)*128;

#pragma unroll
            for (int ks = 0; ks < 4; ks++) {
                // B fragments (shared by both row-blocks)
                int kcB = ks*2 + khalfB;
                uint32_t bh[16], bl[16];
#pragma unroll
                for (int i = 0; i < 4; i++) {
                    uint32_t baddr = boff + i*2048 + ((kcB ^ bsw) << 4);
                    ldsm4(bh[4*i+0], bh[4*i+1], bh[4*i+2], bh[4*i+3],
                          baddr + SM_WH);
                    ldsm4(bl[4*i+0], bl[4*i+1], bl[4*i+2], bl[4*i+3],
                          baddr + SM_WL);
                }

                int kcA = ks*2 + khalfA;
#pragma unroll
                for (int r = 0; r < 2; r++) {
                    int pix = (2*w + r + kh)*PATCH_W + rA + kw;
                    uint32_t aaddr = sb + pix*128 + ((kcA ^ (pix & 7)) << 4);
                    uint32_t ah0, ah1, ah2, ah3, al0, al1, al2, al3;
                    ldsm4(ah0, ah1, ah2, ah3, aaddr + SM_PH);
                    ldsm4(al0, al1, al2, al3, aaddr + SM_PL);
#pragma unroll
                    for (int nt = 0; nt < 8; nt++)
                        mma_bf16(acc[r][nt], ah0, ah1, ah2, ah3,
                                 bh[2*nt], bh[2*nt+1]);
#pragma unroll
                    for (int nt = 0; nt < 8; nt++)
                        mma_bf16(acc[r][nt], ah0, ah1, ah2, ah3,
                                 bl[2*nt], bl[2*nt+1]);
#pragma unroll
                    for (int nt = 0; nt < 8; nt++)
                        mma_bf16(acc[r][nt], al0, al1, al2, al3,
                                 bh[2*nt], bh[2*nt+1]);
                }
            }
        }

        // ---- Epilogue ----
        {
            const float* bias = (const float*)(smem + SM_BIAS);
            int r0 = l >> 2;
            int cp = (l & 3) * 2;
#pragma unroll
            for (int r = 0; r < 2; r++) {
                int oh = oh0 + 2*w + r;
                size_t pbase = (size_t)bb*OCN*SSZ + (size_t)oh*OHW + ow0;
#pragma unroll
                for (int nt = 0; nt < 8; nt++) {
                    int oc = nt*8 + cp;
                    float b0 = bias[oc], b1 = bias[oc+1];
                    float* o0 = out + pbase + (size_t)oc*SSZ;
                    float* o1 = o0 + SSZ;
                    o0[r0]     = acc[r][nt][0] + b0;
                    o1[r0]     = acc[r][nt][1] + b1;
                    o0[r0 + 8] = acc[r][nt][2] + b0;
                    o1[r0 + 8] = acc[r][nt][3] + b1;
                }
            }
        }
    }
}

// ---------------------------------------------------------------------------
extern "C" void kernel_launch(void* const* d_in, const int* in_sizes, int n_in,
                              void* d_out, int out_size) {
    const float* x   = (const float*)d_in[0];  // [8,32,96,96]
    const float* pos = (const float*)d_in[1];  // [64,32,3,3,3]
    const float* val = (const float*)d_in[2];  // [64,32,3,3,3]
    float* out = (float*)d_out;                // [8,64,96,96]

    cudaFuncSetAttribute(pw_mma_kernel,
                         cudaFuncAttributeMaxDynamicSharedMemorySize,
                         SM_TOTAL);

    prep_w_kernel<<<OCN, KK>>>(pos, val);
    prep_img_kernel<<<BATCH*HH, 256>>>(x, pos);
    pw_mma_kernel<<<144, 256, SM_TOTAL>>>(out);
}

// round 9
// speedup vs baseline: 1.0756x; 1.0756x over previous
#include <cuda_runtime.h>
#include <cuda_bf16.h>
#include <cstdint>

// ---------------------------------------------------------------------------
// Problem constants
// ---------------------------------------------------------------------------
#define BATCH 8
#define CIN   32
#define HH    96
#define WW    96
#define OCN   64
#define OHW   96
#define SSZ   (OHW*OHW)      // 9216
#define KK    (CIN*3*3)      // 288

#define TILE_H 16
#define TILE_W 16
#define PATCH_H 18
#define PATCH_W 18
#define NPIX    (PATCH_H*PATCH_W)    // 324

// Dynamic smem layout (bytes) — 113.0KB; 2x(115712+1024) = 233472 = SM limit
#define SM_W      0                   // 2 tap buffers x (hi 8KB + lo 8KB)
#define SM_PH     32768               // patch hi: 324 rows x 128B = 41472
#define SM_PL     74240               // patch lo: 41472
#define SM_TOTAL  115712

// Preprocessed weights: [2 (hi/lo)][9 tap][64 oc][64 k] bf16
__device__ __align__(16) __nv_bfloat16 g_W[2*9*64*64];
__device__ float g_bias[OCN];
// Precomputed NHWC bf16 images: [B][H][W][64ch], ch = [u0(cin)|u1(cin)]
__device__ __align__(16) __nv_bfloat16 g_IMG_H[BATCH*HH*WW*64];
__device__ __align__(16) __nv_bfloat16 g_IMG_L[BATCH*HH*WW*64];

// ---------------------------------------------------------------------------
// Fused prep: blocks 0..767 build the NHWC clipped images; blocks 768..831
// build weight tiles + bias (tree reduction).  grid(832), block(256)
// ---------------------------------------------------------------------------
__global__ __launch_bounds__(256)
void prep_kernel(const float* __restrict__ x,
                 const float* __restrict__ pos,
                 const float* __restrict__ val) {
    const int tid = threadIdx.x;
    const float p0 = pos[0], p1 = pos[1], p2 = pos[2];

    if (blockIdx.x < 768) {
        // ---- image part: one (b, h) row ----
        __shared__ float f[CIN][WW];
        int bh = blockIdx.x;
        int b = bh / HH, h = bh - b*HH;

        const float* xr = x + ((size_t)b*CIN)*HH*WW + (size_t)h*WW;
        for (int idx = tid; idx < CIN*WW; idx += 256) {
            int c = idx / WW, w = idx - c*WW;
            f[c][w] = xr[(size_t)c*HH*WW + w];
        }
        __syncthreads();

        uint32_t* oh32 = (uint32_t*)g_IMG_H + ((size_t)(b*HH + h))*WW*32;
        uint32_t* ol32 = (uint32_t*)g_IMG_L + ((size_t)(b*HH + h))*WW*32;
        for (int idx = tid; idx < WW*32; idx += 256) {
            int w = idx >> 5, j = idx & 31;
            int k0 = 2*j;
            int cin0 = k0 & 31, cin1 = (k0 + 1) & 31;
            float x0 = f[cin0][w], x1 = f[cin1][w];
            float u0 = (k0     < 32) ? fminf(fmaxf(x0, p0), p1)
                                     : fminf(fmaxf(x0, p1), p2);
            float u1 = (k0 + 1 < 32) ? fminf(fmaxf(x1, p0), p1)
                                     : fminf(fmaxf(x1, p1), p2);
            __nv_bfloat162 h2 = __floats2bfloat162_rn(u0, u1);
            float2 hf = __bfloat1622float2(h2);
            __nv_bfloat162 l2 = __floats2bfloat162_rn(u0 - hf.x, u1 - hf.y);
            oh32[idx] = reinterpret_cast<const uint32_t&>(h2);
            ol32[idx] = reinterpret_cast<const uint32_t&>(l2);
        }
    } else {
        // ---- weight part: one oc ----
        __shared__ float red[256];
        int oc = blockIdx.x - 768;
        float part = 0.f;
        for (int k = tid; k < KK; k += 256) {
            const float* p = pos + ((size_t)(oc*KK + k))*3;
            const float* v = val + ((size_t)(oc*KK + k))*3;
            float q0 = p[0], q1 = p[1], q2 = p[2];
            float v0 = v[0], v1 = v[1], v2 = v[2];
            float dp0 = q1 - q0, dp1 = q2 - q1;
            float s0 = (dp0 > 0.f) ? (v1 - v0) / dp0 : 0.f;
            float s1 = (dp1 > 0.f) ? (v2 - v1) / dp1 : 0.f;

            int cin = k / 9;
            int tap = k - cin*9;

            __nv_bfloat16 h0 = __float2bfloat16(s0);
            __nv_bfloat16 l0 = __float2bfloat16(s0 - __bfloat162float(h0));
            __nv_bfloat16 h1 = __float2bfloat16(s1);
            __nv_bfloat16 l1 = __float2bfloat16(s1 - __bfloat162float(h1));

            size_t rb = ((size_t)tap*64 + oc)*64;
            g_W[rb + cin]              = h0;
            g_W[rb + 32 + cin]         = h1;
            g_W[36864 + rb + cin]      = l0;
            g_W[36864 + rb + 32 + cin] = l1;

            part += v0 - s0*q0 - s1*q1;
        }
        red[tid] = part;
        __syncthreads();
#pragma unroll
        for (int s = 128; s > 0; s >>= 1) {
            if (tid < s) red[tid] += red[tid + s];
            __syncthreads();
        }
        if (tid == 0) g_bias[oc] = red[0];
    }
}

// ---------------------------------------------------------------------------
// MMA / cp.async helpers (baseline sm_80+ PTX)
// ---------------------------------------------------------------------------
__device__ __forceinline__ void ldsm4(uint32_t& r0, uint32_t& r1,
                                      uint32_t& r2, uint32_t& r3,
                                      uint32_t addr) {
    asm volatile("ldmatrix.sync.aligned.m8n8.x4.shared.b16 {%0,%1,%2,%3}, [%4];"
                 : "=r"(r0), "=r"(r1), "=r"(r2), "=r"(r3) : "r"(addr));
}
__device__ __forceinline__ void mma_bf16(float* d,
                                         uint32_t a0, uint32_t a1,
                                         uint32_t a2, uint32_t a3,
                                         uint32_t b0, uint32_t b1) {
    asm volatile(
        "mma.sync.aligned.m16n8k16.row.col.f32.bf16.bf16.f32 "
        "{%0,%1,%2,%3}, {%4,%5,%6,%7}, {%8,%9}, {%0,%1,%2,%3};"
        : "+f"(d[0]), "+f"(d[1]), "+f"(d[2]), "+f"(d[3])
        : "r"(a0), "r"(a1), "r"(a2), "r"(a3), "r"(b0), "r"(b1));
}
__device__ __forceinline__ uint32_t smem_u32(const void* p) {
    uint32_t a;
    asm("{ .reg .u64 t; cvta.to.shared.u64 t, %1; cvt.u32.u64 %0, t; }"
        : "=r"(a) : "l"(p));
    return a;
}
__device__ __forceinline__ void cp_async16(uint32_t dst, const void* src,
                                           uint32_t src_size) {
    asm volatile("cp.async.cg.shared.global [%0], [%1], 16, %2;"
                 :: "r"(dst), "l"(src), "r"(src_size) : "memory");
}
__device__ __forceinline__ void cp_commit() {
    asm volatile("cp.async.commit_group;" ::: "memory");
}
__device__ __forceinline__ void cp_wait0() {
    asm volatile("cp.async.wait_group 0;" ::: "memory");
}

// ---------------------------------------------------------------------------
// Weight tap staging: 1024 x 16B chunks (hi 512 + lo 512) into ring buffer.
// ---------------------------------------------------------------------------
__device__ __forceinline__ void stage_tap(uint32_t sb, int tap, int buf,
                                          int tid) {
    const char* gw = (const char*)g_W;
#pragma unroll
    for (int i = 0; i < 4; i++) {
        int idx = tid + i*256;          // 0..1023
        int arr = idx >> 9;             // 0 hi, 1 lo
        int e   = idx & 511;
        int lr  = e >> 3, c = e & 7;    // local row 0..63, chunk 0..7
        const char* src = gw + (arr ? 73728 : 0) + tap*8192 + lr*128 + c*16;
        uint32_t dst = sb + SM_W + buf*16384 + arr*8192
                     + lr*128 + ((c ^ (lr & 7)) << 4);
        cp_async16(dst, src, 16u);
    }
}

// ---------------------------------------------------------------------------
// Main: grid(288), ONE 16x16 tile per block (tile = blockIdx.x; bb in [0,8)).
// 113KB smem -> 2 CTAs/SM; weights streamed per-tap (double-buffered ring).
// 8 warps; warp w owns oh rows {2w, 2w+1} (B frags reused across 2 rows).
// ---------------------------------------------------------------------------
__global__ __launch_bounds__(256, 2)
void pw_mma_kernel(float* __restrict__ out) {
    extern __shared__ char smem[];
    const uint32_t sb = smem_u32(smem);
    const int tid = threadIdx.x;
    const int l   = tid & 31;
    const int w   = tid >> 5;

    // lane constants (validated choreography)
    const int rA     = l & 15;
    const int khalfA = l >> 4;
    const int ocb    = ((l >> 4) & 1)*8 + (l & 7);
    const int khalfB = (l >> 3) & 1;
    const int bsw    = l & 7;

    const char* imgH = (const char*)g_IMG_H;
    const char* imgL = (const char*)g_IMG_L;

    const int tile = blockIdx.x;               // 0..287
    const int bb   = tile / 36;                // batch 0..7
    const int rem  = tile - bb*36;
    const int oh0  = (rem / 6) * TILE_H;
    const int ow0  = (rem - (rem/6)*6) * TILE_W;

    // ---- stage patch (cp.async, swizzled, OOB zero-fill) ----
    for (int idx = tid; idx < 2*NPIX*8; idx += 256) {   // 5184 chunks
        int arr = idx >= NPIX*8;
        int e   = idx - arr*NPIX*8;
        int p   = e >> 3, c = e & 7;
        int ph  = p / PATCH_W;
        int pw  = p - ph*PATCH_W;
        int h   = oh0 - 1 + ph;
        int w2  = ow0 - 1 + pw;
        int inb = ((unsigned)h < HH) && ((unsigned)w2 < WW);
        int hc  = inb ? h : 0;
        int wc  = inb ? w2 : 0;
        const char* src = (arr ? imgL : imgH)
            + ((size_t)((bb*HH + hc)*WW + wc))*128 + c*16;
        uint32_t dst = sb + (arr ? SM_PL : SM_PH)
            + p*128 + ((c ^ (p & 7)) << 4);
        cp_async16(dst, src, inb ? 16u : 0u);
    }
    // ---- stage tap 0 weights into buf 0 ----
    stage_tap(sb, 0, 0, tid);
    cp_commit();
    cp_wait0();
    __syncthreads();

    // ---- 9-tap HMMA, weights prefetched one tap ahead ----
    float acc[2][8][4];
#pragma unroll
    for (int r = 0; r < 2; r++)
#pragma unroll
        for (int nt = 0; nt < 8; nt++)
#pragma unroll
            for (int i = 0; i < 4; i++) acc[r][nt][i] = 0.f;

    for (int tap = 0; tap < 9; tap++) {
        int kh = tap / 3, kw = tap - (tap/3)*3;
        int buf = tap & 1;

        if (tap < 8) {
            stage_tap(sb, tap + 1, buf ^ 1, tid);
            cp_commit();
        }

        uint32_t boff = sb + SM_W + buf*16384 + ocb*128;

#pragma unroll
        for (int ks = 0; ks < 4; ks++) {
            int kcB = ks*2 + khalfB;
            uint32_t bh[16], bl[16];
#pragma unroll
            for (int i = 0; i < 4; i++) {
                uint32_t baddr = boff + i*2048 + ((kcB ^ bsw) << 4);
                ldsm4(bh[4*i+0], bh[4*i+1], bh[4*i+2], bh[4*i+3], baddr);
                ldsm4(bl[4*i+0], bl[4*i+1], bl[4*i+2], bl[4*i+3],
                      baddr + 8192);
            }
            int kcA = ks*2 + khalfA;
#pragma unroll
            for (int r = 0; r < 2; r++) {
                int pix = (2*w + r + kh)*PATCH_W + rA + kw;
                uint32_t aaddr = sb + pix*128 + ((kcA ^ (pix & 7)) << 4);
                uint32_t ah0, ah1, ah2, ah3, al0, al1, al2, al3;
                ldsm4(ah0, ah1, ah2, ah3, aaddr + SM_PH);
                ldsm4(al0, al1, al2, al3, aaddr + SM_PL);
#pragma unroll
                for (int nt = 0; nt < 8; nt++)
                    mma_bf16(acc[r][nt], ah0, ah1, ah2, ah3,
                             bh[2*nt], bh[2*nt+1]);
#pragma unroll
                for (int nt = 0; nt < 8; nt++)
                    mma_bf16(acc[r][nt], ah0, ah1, ah2, ah3,
                             bl[2*nt], bl[2*nt+1]);
#pragma unroll
                for (int nt = 0; nt < 8; nt++)
                    mma_bf16(acc[r][nt], al0, al1, al2, al3,
                             bh[2*nt], bh[2*nt+1]);
            }
        }

        if (tap < 8) {
            cp_wait0();
            __syncthreads();   // next tap's weights visible to all
        }
    }

    // ---- epilogue (bias straight from global; L2-resident) ----
    {
        int r0 = l >> 2;
        int cp = (l & 3) * 2;
#pragma unroll
        for (int r = 0; r < 2; r++) {
            int oh = oh0 + 2*w + r;
            size_t pbase = (size_t)bb*OCN*SSZ + (size_t)oh*OHW + ow0;
#pragma unroll
            for (int nt = 0; nt < 8; nt++) {
                int oc = nt*8 + cp;
                float b0 = __ldg(&g_bias[oc]);
                float b1 = __ldg(&g_bias[oc + 1]);
                float* o0 = out + pbase + (size_t)oc*SSZ;
                float* o1 = o0 + SSZ;
                o0[r0]     = acc[r][nt][0] + b0;
                o1[r0]     = acc[r][nt][1] + b1;
                o0[r0 + 8] = acc[r][nt][2] + b0;
                o1[r0 + 8] = acc[r][nt][3] + b1;
            }
        }
    }
}

// ---------------------------------------------------------------------------
extern "C" void kernel_launch(void* const* d_in, const int* in_sizes, int n_in,
                              void* d_out, int out_size) {
    const float* x   = (const float*)d_in[0];  // [8,32,96,96]
    const float* pos = (const float*)d_in[1];  // [64,32,3,3,3]
    const float* val = (const float*)d_in[2];  // [64,32,3,3,3]
    float* out = (float*)d_out;                // [8,64,96,96]

    cudaFuncSetAttribute(pw_mma_kernel,
                         cudaFuncAttributeMaxDynamicSharedMemorySize,
                         SM_TOTAL);

    prep_kernel<<<832, 256>>>(x, pos, val);
    pw_mma_kernel<<<288, 256, SM_TOTAL>>>(out);
}

// round 10
// speedup vs baseline: 1.3384x; 1.2443x over previous
#include <cuda_runtime.h>
#include <cuda_fp16.h>
#include <cstdint>

// ---------------------------------------------------------------------------
// Problem constants
// ---------------------------------------------------------------------------
#define BATCH 8
#define CIN   32
#define HH    96
#define WW    96
#define OCN   64
#define OHW   96
#define SSZ   (OHW*OHW)      // 9216
#define KK    (CIN*3*3)      // 288

#define TILE_H 16
#define TILE_W 16
#define PATCH_H 18
#define PATCH_W 18
#define NPIX    (PATCH_H*PATCH_W)    // 324

// Dynamic smem layout (bytes) — 72.5KB => 2 CTAs/SM easily
#define SM_W      0                   // 2 tap buffers x (Wh 8KB + Wl 8KB)
#define SM_P      32768               // patch fp16: 324 rows x 128B = 41472
#define SM_TOTAL  74240

// Preprocessed weights: [2 (hi/lo)][9 tap][64 oc][64 k] fp16
__device__ __align__(16) __half g_W[2*9*64*64];
__device__ float g_bias[OCN];
// Precomputed NHWC fp16 image: [B][H][W][64ch], ch = [u0(cin)|u1(cin)]
__device__ __align__(16) __half g_IMG[BATCH*HH*WW*64];

// ---------------------------------------------------------------------------
// Fused prep: blocks 0..767 build the NHWC clipped image; blocks 768..831
// build weight tiles + bias (tree reduction).  grid(832), block(256)
// ---------------------------------------------------------------------------
__global__ __launch_bounds__(256)
void prep_kernel(const float* __restrict__ x,
                 const float* __restrict__ pos,
                 const float* __restrict__ val) {
    const int tid = threadIdx.x;
    const float p0 = pos[0], p1 = pos[1], p2 = pos[2];

    if (blockIdx.x < 768) {
        // ---- image part: one (b, h) row ----
        __shared__ float f[CIN][WW];
        int bh = blockIdx.x;
        int b = bh / HH, h = bh - b*HH;

        const float* xr = x + ((size_t)b*CIN)*HH*WW + (size_t)h*WW;
        for (int idx = tid; idx < CIN*WW; idx += 256) {
            int c = idx / WW, w = idx - c*WW;
            f[c][w] = xr[(size_t)c*HH*WW + w];
        }
        __syncthreads();

        uint32_t* o32 = (uint32_t*)g_IMG + ((size_t)(b*HH + h))*WW*32;
        for (int idx = tid; idx < WW*32; idx += 256) {
            int w = idx >> 5, j = idx & 31;
            int k0 = 2*j;
            int cin0 = k0 & 31, cin1 = (k0 + 1) & 31;
            float x0 = f[cin0][w], x1 = f[cin1][w];
            float u0 = (k0     < 32) ? fminf(fmaxf(x0, p0), p1)
                                     : fminf(fmaxf(x0, p1), p2);
            float u1 = (k0 + 1 < 32) ? fminf(fmaxf(x1, p0), p1)
                                     : fminf(fmaxf(x1, p1), p2);
            __half2 h2 = __floats2half2_rn(u0, u1);
            o32[idx] = reinterpret_cast<const uint32_t&>(h2);
        }
    } else {
        // ---- weight part: one oc ----
        __shared__ float red[256];
        int oc = blockIdx.x - 768;
        float part = 0.f;
        for (int k = tid; k < KK; k += 256) {
            const float* p = pos + ((size_t)(oc*KK + k))*3;
            const float* v = val + ((size_t)(oc*KK + k))*3;
            float q0 = p[0], q1 = p[1], q2 = p[2];
            float v0 = v[0], v1 = v[1], v2 = v[2];
            float dp0 = q1 - q0, dp1 = q2 - q1;
            float s0 = (dp0 > 0.f) ? (v1 - v0) / dp0 : 0.f;
            float s1 = (dp1 > 0.f) ? (v2 - v1) / dp1 : 0.f;

            int cin = k / 9;
            int tap = k - cin*9;

            __half h0 = __float2half(s0);
            __half l0 = __float2half(s0 - __half2float(h0));
            __half h1 = __float2half(s1);
            __half l1 = __float2half(s1 - __half2float(h1));

            size_t rb = ((size_t)tap*64 + oc)*64;
            g_W[rb + cin]              = h0;
            g_W[rb + 32 + cin]         = h1;
            g_W[36864 + rb + cin]      = l0;
            g_W[36864 + rb + 32 + cin] = l1;

            part += v0 - s0*q0 - s1*q1;
        }
        red[tid] = part;
        __syncthreads();
#pragma unroll
        for (int s = 128; s > 0; s >>= 1) {
            if (tid < s) red[tid] += red[tid + s];
            __syncthreads();
        }
        if (tid == 0) g_bias[oc] = red[0];
    }
}

// ---------------------------------------------------------------------------
// MMA / cp.async helpers (baseline sm_80+ PTX)
// ---------------------------------------------------------------------------
__device__ __forceinline__ void ldsm4(uint32_t& r0, uint32_t& r1,
                                      uint32_t& r2, uint32_t& r3,
                                      uint32_t addr) {
    asm volatile("ldmatrix.sync.aligned.m8n8.x4.shared.b16 {%0,%1,%2,%3}, [%4];"
                 : "=r"(r0), "=r"(r1), "=r"(r2), "=r"(r3) : "r"(addr));
}
__device__ __forceinline__ void mma_f16(float* d,
                                        uint32_t a0, uint32_t a1,
                                        uint32_t a2, uint32_t a3,
                                        uint32_t b0, uint32_t b1) {
    asm volatile(
        "mma.sync.aligned.m16n8k16.row.col.f32.f16.f16.f32 "
        "{%0,%1,%2,%3}, {%4,%5,%6,%7}, {%8,%9}, {%0,%1,%2,%3};"
        : "+f"(d[0]), "+f"(d[1]), "+f"(d[2]), "+f"(d[3])
        : "r"(a0), "r"(a1), "r"(a2), "r"(a3), "r"(b0), "r"(b1));
}
__device__ __forceinline__ uint32_t smem_u32(const void* p) {
    uint32_t a;
    asm("{ .reg .u64 t; cvta.to.shared.u64 t, %1; cvt.u32.u64 %0, t; }"
        : "=r"(a) : "l"(p));
    return a;
}
__device__ __forceinline__ void cp_async16(uint32_t dst, const void* src,
                                           uint32_t src_size) {
    asm volatile("cp.async.cg.shared.global [%0], [%1], 16, %2;"
                 :: "r"(dst), "l"(src), "r"(src_size) : "memory");
}
__device__ __forceinline__ void cp_commit() {
    asm volatile("cp.async.commit_group;" ::: "memory");
}
__device__ __forceinline__ void cp_wait0() {
    asm volatile("cp.async.wait_group 0;" ::: "memory");
}

// ---------------------------------------------------------------------------
// Weight tap staging: 1024 x 16B chunks (Wh 512 + Wl 512) into ring buffer.
// ---------------------------------------------------------------------------
__device__ __forceinline__ void stage_tap(uint32_t sb, int tap, int buf,
                                          int tid) {
    const char* gw = (const char*)g_W;
#pragma unroll
    for (int i = 0; i < 4; i++) {
        int idx = tid + i*256;          // 0..1023
        int arr = idx >> 9;             // 0 hi, 1 lo
        int e   = idx & 511;
        int lr  = e >> 3, c = e & 7;    // local row 0..63, chunk 0..7
        const char* src = gw + (arr ? 73728 : 0) + tap*8192 + lr*128 + c*16;
        uint32_t dst = sb + SM_W + buf*16384 + arr*8192
                     + lr*128 + ((c ^ (lr & 7)) << 4);
        cp_async16(dst, src, 16u);
    }
}

// ---------------------------------------------------------------------------
// Main: grid(288), one 16x16 tile per block; fp16 A (single) x fp16 W (hi/lo).
// 72.5KB smem -> 2 CTAs/SM; weights streamed per-tap (double-buffered ring).
// 8 warps; warp w owns oh rows {2w, 2w+1} (B frags reused across 2 rows).
// ---------------------------------------------------------------------------
__global__ __launch_bounds__(256, 2)
void pw_mma_kernel(float* __restrict__ out) {
    extern __shared__ char smem[];
    const uint32_t sb = smem_u32(smem);
    const int tid = threadIdx.x;
    const int l   = tid & 31;
    const int w   = tid >> 5;

    // lane constants (validated choreography)
    const int rA     = l & 15;
    const int khalfA = l >> 4;
    const int ocb    = ((l >> 4) & 1)*8 + (l & 7);
    const int khalfB = (l >> 3) & 1;
    const int bsw    = l & 7;

    const char* img = (const char*)g_IMG;

    const int tile = blockIdx.x;               // 0..287
    const int bb   = tile / 36;                // batch 0..7
    const int rem  = tile - bb*36;
    const int oh0  = (rem / 6) * TILE_H;
    const int ow0  = (rem - (rem/6)*6) * TILE_W;

    // ---- stage patch (cp.async, swizzled, OOB zero-fill) ----
    for (int idx = tid; idx < NPIX*8; idx += 256) {   // 2592 chunks
        int p   = idx >> 3, c = idx & 7;
        int ph  = p / PATCH_W;
        int pw  = p - ph*PATCH_W;
        int h   = oh0 - 1 + ph;
        int w2  = ow0 - 1 + pw;
        int inb = ((unsigned)h < HH) && ((unsigned)w2 < WW);
        int hc  = inb ? h : 0;
        int wc  = inb ? w2 : 0;
        const char* src = img + ((size_t)((bb*HH + hc)*WW + wc))*128 + c*16;
        uint32_t dst = sb + SM_P + p*128 + ((c ^ (p & 7)) << 4);
        cp_async16(dst, src, inb ? 16u : 0u);
    }
    // ---- stage tap 0 weights into buf 0 ----
    stage_tap(sb, 0, 0, tid);
    cp_commit();
    cp_wait0();
    __syncthreads();

    // ---- 9-tap HMMA, weights prefetched one tap ahead ----
    float acc[2][8][4];
#pragma unroll
    for (int r = 0; r < 2; r++)
#pragma unroll
        for (int nt = 0; nt < 8; nt++)
#pragma unroll
            for (int i = 0; i < 4; i++) acc[r][nt][i] = 0.f;

    for (int tap = 0; tap < 9; tap++) {
        int kh = tap / 3, kw = tap - (tap/3)*3;
        int buf = tap & 1;

        if (tap < 8) {
            stage_tap(sb, tap + 1, buf ^ 1, tid);
            cp_commit();
        }

        uint32_t boff = sb + SM_W + buf*16384 + ocb*128;

#pragma unroll
        for (int ks = 0; ks < 4; ks++) {
            int kcB = ks*2 + khalfB;
            uint32_t bh[16], bl[16];
#pragma unroll
            for (int i = 0; i < 4; i++) {
                uint32_t baddr = boff + i*2048 + ((kcB ^ bsw) << 4);
                ldsm4(bh[4*i+0], bh[4*i+1], bh[4*i+2], bh[4*i+3], baddr);
                ldsm4(bl[4*i+0], bl[4*i+1], bl[4*i+2], bl[4*i+3],
                      baddr + 8192);
            }
            int kcA = ks*2 + khalfA;
#pragma unroll
            for (int r = 0; r < 2; r++) {
                int pix = (2*w + r + kh)*PATCH_W + rA + kw;
                uint32_t aaddr = sb + SM_P + pix*128
                               + ((kcA ^ (pix & 7)) << 4);
                uint32_t a0, a1, a2, a3;
                ldsm4(a0, a1, a2, a3, aaddr);
#pragma unroll
                for (int nt = 0; nt < 8; nt++)
                    mma_f16(acc[r][nt], a0, a1, a2, a3,
                            bh[2*nt], bh[2*nt+1]);
#pragma unroll
                for (int nt = 0; nt < 8; nt++)
                    mma_f16(acc[r][nt], a0, a1, a2, a3,
                            bl[2*nt], bl[2*nt+1]);
            }
        }

        if (tap < 8) {
            cp_wait0();
            __syncthreads();   // next tap's weights visible to all
        }
    }

    // ---- epilogue (bias straight from global; L2-resident) ----
    {
        int r0 = l >> 2;
        int cp = (l & 3) * 2;
#pragma unroll
        for (int r = 0; r < 2; r++) {
            int oh = oh0 + 2*w + r;
            size_t pbase = (size_t)bb*OCN*SSZ + (size_t)oh*OHW + ow0;
#pragma unroll
            for (int nt = 0; nt < 8; nt++) {
                int oc = nt*8 + cp;
                float b0 = __ldg(&g_bias[oc]);
                float b1 = __ldg(&g_bias[oc + 1]);
                float* o0 = out + pbase + (size_t)oc*SSZ;
                float* o1 = o0 + SSZ;
                o0[r0]     = acc[r][nt][0] + b0;
                o1[r0]     = acc[r][nt][1] + b1;
                o0[r0 + 8] = acc[r][nt][2] + b0;
                o1[r0 + 8] = acc[r][nt][3] + b1;
            }
        }
    }
}

// ---------------------------------------------------------------------------
extern "C" void kernel_launch(void* const* d_in, const int* in_sizes, int n_in,
                              void* d_out, int out_size) {
    const float* x   = (const float*)d_in[0];  // [8,32,96,96]
    const float* pos = (const float*)d_in[1];  // [64,32,3,3,3]
    const float* val = (const float*)d_in[2];  // [64,32,3,3,3]
    float* out = (float*)d_out;                // [8,64,96,96]

    cudaFuncSetAttribute(pw_mma_kernel,
                         cudaFuncAttributeMaxDynamicSharedMemorySize,
                         SM_TOTAL);

    prep_kernel<<<832, 256>>>(x, pos, val);
    pw_mma_kernel<<<288, 256, SM_TOTAL>>>(out);
}

// round 11
// speedup vs baseline: 1.5855x; 1.1847x over previous
#include <cuda_runtime.h>
#include <cuda_fp16.h>
#include <cstdint>

// ---------------------------------------------------------------------------
// Problem constants
// ---------------------------------------------------------------------------
#define BATCH 8
#define CIN   32
#define HH    96
#define WW    96
#define OCN   64
#define OHW   96
#define SSZ   (OHW*OHW)      // 9216
#define KK    (CIN*3*3)      // 288

#define TILE_H 16
#define TILE_W 16
#define PATCH_H 18
#define PATCH_W 18
#define NPIX    (PATCH_H*PATCH_W)    // 324

// Dynamic smem layout (bytes) — 72.5KB => 2 CTAs/SM
#define SM_W      0                   // 2 tap buffers x (Wh 8KB + Wl 8KB)
#define SM_P      32768               // patch fp16: 324 rows x 128B = 41472
#define SM_TOTAL  74240

// Preprocessed weights: [2 (hi/lo)][9 tap][64 oc][64 k] fp16
__device__ __align__(16) __half g_W[2*9*64*64];
__device__ float g_bias[OCN];

// ---------------------------------------------------------------------------
// Weight prep only: grid(64), block(256); tree-reduced bias.
// ---------------------------------------------------------------------------
__global__ __launch_bounds__(256)
void prep_w_kernel(const float* __restrict__ pos,
                   const float* __restrict__ val) {
    __shared__ float red[256];
    const int tid = threadIdx.x;
    const int oc  = blockIdx.x;
    float part = 0.f;
    for (int k = tid; k < KK; k += 256) {
        const float* p = pos + ((size_t)(oc*KK + k))*3;
        const float* v = val + ((size_t)(oc*KK + k))*3;
        float q0 = p[0], q1 = p[1], q2 = p[2];
        float v0 = v[0], v1 = v[1], v2 = v[2];
        float dp0 = q1 - q0, dp1 = q2 - q1;
        float s0 = (dp0 > 0.f) ? (v1 - v0) / dp0 : 0.f;
        float s1 = (dp1 > 0.f) ? (v2 - v1) / dp1 : 0.f;

        int cin = k / 9;
        int tap = k - cin*9;

        __half h0 = __float2half(s0);
        __half l0 = __float2half(s0 - __half2float(h0));
        __half h1 = __float2half(s1);
        __half l1 = __float2half(s1 - __half2float(h1));

        size_t rb = ((size_t)tap*64 + oc)*64;
        g_W[rb + cin]              = h0;
        g_W[rb + 32 + cin]         = h1;
        g_W[36864 + rb + cin]      = l0;
        g_W[36864 + rb + 32 + cin] = l1;

        part += v0 - s0*q0 - s1*q1;
    }
    red[tid] = part;
    __syncthreads();
#pragma unroll
    for (int s = 128; s > 0; s >>= 1) {
        if (tid < s) red[tid] += red[tid + s];
        __syncthreads();
    }
    if (tid == 0) g_bias[oc] = red[0];
}

// ---------------------------------------------------------------------------
// MMA / cp.async helpers (baseline sm_80+ PTX)
// ---------------------------------------------------------------------------
__device__ __forceinline__ void ldsm4(uint32_t& r0, uint32_t& r1,
                                      uint32_t& r2, uint32_t& r3,
                                      uint32_t addr) {
    asm volatile("ldmatrix.sync.aligned.m8n8.x4.shared.b16 {%0,%1,%2,%3}, [%4];"
                 : "=r"(r0), "=r"(r1), "=r"(r2), "=r"(r3) : "r"(addr));
}
__device__ __forceinline__ void mma_f16(float* d,
                                        uint32_t a0, uint32_t a1,
                                        uint32_t a2, uint32_t a3,
                                        uint32_t b0, uint32_t b1) {
    asm volatile(
        "mma.sync.aligned.m16n8k16.row.col.f32.f16.f16.f32 "
        "{%0,%1,%2,%3}, {%4,%5,%6,%7}, {%8,%9}, {%0,%1,%2,%3};"
        : "+f"(d[0]), "+f"(d[1]), "+f"(d[2]), "+f"(d[3])
        : "r"(a0), "r"(a1), "r"(a2), "r"(a3), "r"(b0), "r"(b1));
}
__device__ __forceinline__ uint32_t smem_u32(const void* p) {
    uint32_t a;
    asm("{ .reg .u64 t; cvta.to.shared.u64 t, %1; cvt.u32.u64 %0, t; }"
        : "=r"(a) : "l"(p));
    return a;
}
__device__ __forceinline__ void cp_async16(uint32_t dst, const void* src,
                                           uint32_t src_size) {
    asm volatile("cp.async.cg.shared.global [%0], [%1], 16, %2;"
                 :: "r"(dst), "l"(src), "r"(src_size) : "memory");
}
__device__ __forceinline__ void cp_commit() {
    asm volatile("cp.async.commit_group;" ::: "memory");
}
__device__ __forceinline__ void cp_wait0() {
    asm volatile("cp.async.wait_group 0;" ::: "memory");
}
__device__ __forceinline__ uint32_t h2_as_u32(__half2 v) {
    return reinterpret_cast<const uint32_t&>(v);
}

// ---------------------------------------------------------------------------
// Weight tap staging: 1024 x 16B chunks (Wh 512 + Wl 512) into ring buffer.
// ---------------------------------------------------------------------------
__device__ __forceinline__ void stage_tap(uint32_t sb, int tap, int buf,
                                          int tid) {
    const char* gw = (const char*)g_W;
#pragma unroll
    for (int i = 0; i < 4; i++) {
        int idx = tid + i*256;          // 0..1023
        int arr = idx >> 9;             // 0 hi, 1 lo
        int e   = idx & 511;
        int lr  = e >> 3, c = e & 7;    // local row 0..63, chunk 0..7
        const char* src = gw + (arr ? 73728 : 0) + tap*8192 + lr*128 + c*16;
        uint32_t dst = sb + SM_W + buf*16384 + arr*8192
                     + lr*128 + ((c ^ (lr & 7)) << 4);
        cp_async16(dst, src, 16u);
    }
}

// ---------------------------------------------------------------------------
// Main: grid(288), one 16x16 tile per block; fp16 A x fp16 W (hi/lo split).
// In-kernel clamp/convert staging (no image prep pass).
// 8 warps re-split: warp = (whalf: oc half, wrow: 4 oh rows). B ldsm halved.
// ---------------------------------------------------------------------------
__global__ __launch_bounds__(256, 2)
void pw_mma_kernel(const float* __restrict__ x,
                   const float* __restrict__ pos,
                   float* __restrict__ out) {
    extern __shared__ char smem[];
    const uint32_t sb = smem_u32(smem);
    const int tid = threadIdx.x;
    const int l   = tid & 31;
    const int w   = tid >> 5;
    const int whalf = w >> 2;           // oc half (0: oc0-31, 1: oc32-63)
    const int wrow  = w & 3;            // 4 oh rows {4*wrow .. 4*wrow+3}

    // lane constants (validated choreography)
    const int rA     = l & 15;
    const int khalfA = l >> 4;
    const int ocb    = ((l >> 4) & 1)*8 + (l & 7);
    const int khalfB = (l >> 3) & 1;
    const int bsw    = l & 7;

    const int tile = blockIdx.x;               // 0..287
    const int bb   = tile / 36;                // batch 0..7
    const int rem  = tile - bb*36;
    const int oh0  = (rem / 6) * TILE_H;
    const int ow0  = (rem - (rem/6)*6) * TILE_W;

    const float P0 = pos[0], P1 = pos[1], P2 = pos[2];

    // ---- stage tap 0 weights (async) while we convert the patch ----
    stage_tap(sb, 0, 0, tid);
    cp_commit();

    // ---- in-kernel patch staging: fp32 x -> clamped fp16, swizzled ----
    {
        const float* xb = x + (size_t)bb * (CIN*HH*WW);
        // per-thread pixel slots (p = tid, tid+256)
        int   offp[2];  int inbp[2];
#pragma unroll
        for (int s = 0; s < 2; s++) {
            int p  = tid + s*256;
            int ph = p / PATCH_W;
            int pw = p - ph*PATCH_W;
            int h  = oh0 - 1 + ph;
            int w2 = ow0 - 1 + pw;
            inbp[s] = (p < NPIX) && ((unsigned)h < HH) && ((unsigned)w2 < WW);
            offp[s] = (inbp[s] ? h*WW + w2 : 0);
        }
#pragma unroll 4
        for (int j = 0; j < 16; j++) {          // cin pair (2j, 2j+1)
            const float* pl0 = xb + (size_t)(2*j)*HH*WW;
            const float* pl1 = pl0 + HH*WW;
#pragma unroll
            for (int s = 0; s < 2; s++) {
                int p = tid + s*256;
                if (p >= NPIX) break;
                float x0 = inbp[s] ? pl0[offp[s]] : 0.f;
                float x1 = inbp[s] ? pl1[offp[s]] : 0.f;
                __half2 a = __floats2half2_rn(fminf(fmaxf(x0, P0), P1),
                                              fminf(fmaxf(x1, P0), P1));
                __half2 b = __floats2half2_rn(fminf(fmaxf(x0, P1), P2),
                                              fminf(fmaxf(x1, P1), P2));
                int c0 = j >> 2;                // chunk for group 0
                int c1 = c0 + 4;                // chunk for group 1
                int sub = (j & 3) * 4;
                *(uint32_t*)(smem + SM_P + p*128
                             + ((c0 ^ (p & 7)) << 4) + sub) = h2_as_u32(a);
                *(uint32_t*)(smem + SM_P + p*128
                             + ((c1 ^ (p & 7)) << 4) + sub) = h2_as_u32(b);
            }
        }
    }
    cp_wait0();
    __syncthreads();

    // ---- 9-tap HMMA, weights prefetched one tap ahead ----
    float acc[4][4][4];                 // [row r][nt][frag]
#pragma unroll
    for (int r = 0; r < 4; r++)
#pragma unroll
        for (int nt = 0; nt < 4; nt++)
#pragma unroll
            for (int i = 0; i < 4; i++) acc[r][nt][i] = 0.f;

    for (int tap = 0; tap < 9; tap++) {
        int kh = tap / 3, kw = tap - (tap/3)*3;
        int buf = tap & 1;

        if (tap < 8) {
            stage_tap(sb, tap + 1, buf ^ 1, tid);
            cp_commit();
        }

        uint32_t boff = sb + SM_W + buf*16384 + (whalf*32 + ocb)*128;

#pragma unroll
        for (int ks = 0; ks < 4; ks++) {
            int kcB = ks*2 + khalfB;
            uint32_t bh[8], bl[8];
#pragma unroll
            for (int i = 0; i < 2; i++) {       // 32 oc = 2 x 16-row blocks
                uint32_t baddr = boff + i*2048 + ((kcB ^ bsw) << 4);
                ldsm4(bh[4*i+0], bh[4*i+1], bh[4*i+2], bh[4*i+3], baddr);
                ldsm4(bl[4*i+0], bl[4*i+1], bl[4*i+2], bl[4*i+3],
                      baddr + 8192);
            }
            int kcA = ks*2 + khalfA;
#pragma unroll
            for (int r = 0; r < 4; r++) {
                int pix = (4*wrow + r + kh)*PATCH_W + rA + kw;
                uint32_t aaddr = sb + SM_P + pix*128
                               + ((kcA ^ (pix & 7)) << 4);
                uint32_t a0, a1, a2, a3;
                ldsm4(a0, a1, a2, a3, aaddr);
#pragma unroll
                for (int nt = 0; nt < 4; nt++)
                    mma_f16(acc[r][nt], a0, a1, a2, a3,
                            bh[2*nt], bh[2*nt+1]);
#pragma unroll
                for (int nt = 0; nt < 4; nt++)
                    mma_f16(acc[r][nt], a0, a1, a2, a3,
                            bl[2*nt], bl[2*nt+1]);
            }
        }

        if (tap < 8) {
            cp_wait0();
            __syncthreads();   // next tap's weights visible to all
        }
    }

    // ---- epilogue (bias from global; L2-resident) ----
    {
        int r0 = l >> 2;
        int cp = (l & 3) * 2;
#pragma unroll
        for (int r = 0; r < 4; r++) {
            int oh = oh0 + 4*wrow + r;
            size_t pbase = (size_t)bb*OCN*SSZ + (size_t)oh*OHW + ow0;
#pragma unroll
            for (int nt = 0; nt < 4; nt++) {
                int oc = whalf*32 + nt*8 + cp;
                float b0 = __ldg(&g_bias[oc]);
                float b1 = __ldg(&g_bias[oc + 1]);
                float* o0 = out + pbase + (size_t)oc*SSZ;
                float* o1 = o0 + SSZ;
                o0[r0]     = acc[r][nt][0] + b0;
                o1[r0]     = acc[r][nt][1] + b1;
                o0[r0 + 8] = acc[r][nt][2] + b0;
                o1[r0 + 8] = acc[r][nt][3] + b1;
            }
        }
    }
}

// ---------------------------------------------------------------------------
extern "C" void kernel_launch(void* const* d_in, const int* in_sizes, int n_in,
                              void* d_out, int out_size) {
    const float* x   = (const float*)d_in[0];  // [8,32,96,96]
    const float* pos = (const float*)d_in[1];  // [64,32,3,3,3]
    const float* val = (const float*)d_in[2];  // [64,32,3,3,3]
    float* out = (float*)d_out;                // [8,64,96,96]

    cudaFuncSetAttribute(pw_mma_kernel,
                         cudaFuncAttributeMaxDynamicSharedMemorySize,
                         SM_TOTAL);

    prep_w_kernel<<<OCN, 256>>>(pos, val);
    pw_mma_kernel<<<288, 256, SM_TOTAL>>>(x, pos, out);
}

// round 12
// speedup vs baseline: 2.3793x; 1.5006x over previous
#include <cuda_runtime.h>
#include <cuda_fp16.h>
#include <cstdint>

// ---------------------------------------------------------------------------
// Problem constants
// ---------------------------------------------------------------------------
#define BATCH 8
#define CIN   32
#define HH    96
#define WW    96
#define OCN   64
#define OHW   96
#define SSZ   (OHW*OHW)      // 9216
#define KK    (CIN*3*3)      // 288

#define TILE_H 16
#define TILE_W 16
#define PATCH_H 18
#define PATCH_W 18
#define NPIX    (PATCH_H*PATCH_W)    // 324

// Dynamic smem layout (bytes) — 112.5KB; (115200+1024)*2 = 232448 <= 233472
#define SM_W      0                   // resident weights: 9*64 rows x 128B
#define SM_P      73728               // patch fp16: 324 rows x 128B = 41472
#define SM_TOTAL  115200

// Preprocessed weights: [9 tap][64 oc][64 k] fp16 (k = cin | 32+cin)
__device__ __align__(16) __half g_W[9*64*64];
__device__ float g_bias[OCN];

// ---------------------------------------------------------------------------
// Weight prep: grid(64), block(256); tree-reduced bias.
// ---------------------------------------------------------------------------
__global__ __launch_bounds__(256)
void prep_w_kernel(const float* __restrict__ pos,
                   const float* __restrict__ val) {
    __shared__ float red[256];
    const int tid = threadIdx.x;
    const int oc  = blockIdx.x;
    float part = 0.f;
    for (int k = tid; k < KK; k += 256) {
        const float* p = pos + ((size_t)(oc*KK + k))*3;
        const float* v = val + ((size_t)(oc*KK + k))*3;
        float q0 = p[0], q1 = p[1], q2 = p[2];
        float v0 = v[0], v1 = v[1], v2 = v[2];
        float dp0 = q1 - q0, dp1 = q2 - q1;
        float s0 = (dp0 > 0.f) ? (v1 - v0) / dp0 : 0.f;
        float s1 = (dp1 > 0.f) ? (v2 - v1) / dp1 : 0.f;

        int cin = k / 9;
        int tap = k - cin*9;

        size_t rb = ((size_t)tap*64 + oc)*64;
        g_W[rb + cin]      = __float2half(s0);
        g_W[rb + 32 + cin] = __float2half(s1);

        part += v0 - s0*q0 - s1*q1;
    }
    red[tid] = part;
    __syncthreads();
#pragma unroll
    for (int s = 128; s > 0; s >>= 1) {
        if (tid < s) red[tid] += red[tid + s];
        __syncthreads();
    }
    if (tid == 0) g_bias[oc] = red[0];
}

// ---------------------------------------------------------------------------
// MMA / cp.async helpers (baseline sm_80+ PTX)
// ---------------------------------------------------------------------------
__device__ __forceinline__ void ldsm4(uint32_t& r0, uint32_t& r1,
                                      uint32_t& r2, uint32_t& r3,
                                      uint32_t addr) {
    asm volatile("ldmatrix.sync.aligned.m8n8.x4.shared.b16 {%0,%1,%2,%3}, [%4];"
                 : "=r"(r0), "=r"(r1), "=r"(r2), "=r"(r3) : "r"(addr));
}
__device__ __forceinline__ void mma_f16(float* d,
                                        uint32_t a0, uint32_t a1,
                                        uint32_t a2, uint32_t a3,
                                        uint32_t b0, uint32_t b1) {
    asm volatile(
        "mma.sync.aligned.m16n8k16.row.col.f32.f16.f16.f32 "
        "{%0,%1,%2,%3}, {%4,%5,%6,%7}, {%8,%9}, {%0,%1,%2,%3};"
        : "+f"(d[0]), "+f"(d[1]), "+f"(d[2]), "+f"(d[3])
        : "r"(a0), "r"(a1), "r"(a2), "r"(a3), "r"(b0), "r"(b1));
}
__device__ __forceinline__ uint32_t smem_u32(const void* p) {
    uint32_t a;
    asm("{ .reg .u64 t; cvta.to.shared.u64 t, %1; cvt.u32.u64 %0, t; }"
        : "=r"(a) : "l"(p));
    return a;
}
__device__ __forceinline__ void cp_async16(uint32_t dst, const void* src) {
    asm volatile("cp.async.cg.shared.global [%0], [%1], 16;"
                 :: "r"(dst), "l"(src) : "memory");
}
__device__ __forceinline__ void cp_commit() {
    asm volatile("cp.async.commit_group;" ::: "memory");
}
__device__ __forceinline__ void cp_wait0() {
    asm volatile("cp.async.wait_group 0;" ::: "memory");
}
__device__ __forceinline__ uint32_t h2_as_u32(__half2 v) {
    return reinterpret_cast<const uint32_t&>(v);
}

// ---------------------------------------------------------------------------
// Main: grid(288), one 16x16 tile per block; single fp16 A x fp16 W group.
// ALL weights smem-resident (staged once, cp.async) -> barrier-free tap loop.
// 8 warps: warp = (whalf: oc half, wrow: 4 oh rows).
// ---------------------------------------------------------------------------
__global__ __launch_bounds__(256, 2)
void pw_mma_kernel(const float* __restrict__ x,
                   const float* __restrict__ pos,
                   float* __restrict__ out) {
    extern __shared__ char smem[];
    const uint32_t sb = smem_u32(smem);
    const int tid = threadIdx.x;
    const int l   = tid & 31;
    const int w   = tid >> 5;
    const int whalf = w >> 2;           // oc half (0: oc0-31, 1: oc32-63)
    const int wrow  = w & 3;            // 4 oh rows {4*wrow .. 4*wrow+3}

    // lane constants (validated choreography)
    const int rA     = l & 15;
    const int khalfA = l >> 4;
    const int ocb    = ((l >> 4) & 1)*8 + (l & 7);
    const int khalfB = (l >> 3) & 1;
    const int bsw    = l & 7;

    const int tile = blockIdx.x;               // 0..287
    const int bb   = tile / 36;                // batch 0..7
    const int rem  = tile - bb*36;
    const int oh0  = (rem / 6) * TILE_H;
    const int ow0  = (rem - (rem/6)*6) * TILE_W;

    const float P0f = pos[0], P1f = pos[1], P2f = pos[2];
    const __half2 P0 = __float2half2_rn(P0f);
    const __half2 P1 = __float2half2_rn(P1f);
    const __half2 P2 = __float2half2_rn(P2f);

    // ---- stage ALL weights (cp.async, swizzled) — overlaps patch work ----
    {
        const char* gw = (const char*)g_W;
        for (int idx = tid; idx < 4608; idx += 256) {  // 576 rows x 8 chunks
            int row = idx >> 3, c = idx & 7;
            cp_async16(sb + SM_W + row*128 + ((c ^ (row & 7)) << 4),
                       gw + row*128 + c*16);
        }
        cp_commit();
    }

    // ---- in-kernel patch staging: fp32 x -> clamped fp16, swizzled ----
    {
        const float* xb = x + (size_t)bb * (CIN*HH*WW);
        int offp[2]; int inbp[2];
#pragma unroll
        for (int s = 0; s < 2; s++) {
            int p  = tid + s*256;
            int ph = p / PATCH_W;
            int pw = p - ph*PATCH_W;
            int h  = oh0 - 1 + ph;
            int w2 = ow0 - 1 + pw;
            inbp[s] = (p < NPIX) && ((unsigned)h < HH) && ((unsigned)w2 < WW);
            offp[s] = (inbp[s] ? h*WW + w2 : 0);
        }
#pragma unroll
        for (int jb = 0; jb < 4; jb++) {        // 8 channels per block
#pragma unroll
            for (int s = 0; s < 2; s++) {
                int p = tid + s*256;
                if (p >= NPIX) break;
                uint32_t qa[4], qb[4];
#pragma unroll
                for (int q = 0; q < 4; q++) {
                    int ch = jb*8 + 2*q;
                    float x0 = inbp[s] ? xb[(size_t)ch*HH*WW + offp[s]] : 0.f;
                    float x1 = inbp[s] ? xb[(size_t)(ch+1)*HH*WW + offp[s]]
                                       : 0.f;
                    __half2 hv = __floats2half2_rn(x0, x1);
                    qa[q] = h2_as_u32(__hmin2(__hmax2(hv, P0), P1));
                    qb[q] = h2_as_u32(__hmin2(__hmax2(hv, P1), P2));
                }
                int c0 = jb, c1 = jb + 4;
                *(uint4*)(smem + SM_P + p*128 + ((c0 ^ (p & 7)) << 4)) =
                    make_uint4(qa[0], qa[1], qa[2], qa[3]);
                *(uint4*)(smem + SM_P + p*128 + ((c1 ^ (p & 7)) << 4)) =
                    make_uint4(qb[0], qb[1], qb[2], qb[3]);
            }
        }
    }
    cp_wait0();
    __syncthreads();

    // ---- 9-tap HMMA, fully barrier-free ----
    float acc[4][4][4];                 // [row r][nt][frag]
#pragma unroll
    for (int r = 0; r < 4; r++)
#pragma unroll
        for (int nt = 0; nt < 4; nt++)
#pragma unroll
            for (int i = 0; i < 4; i++) acc[r][nt][i] = 0.f;

    for (int tap = 0; tap < 9; tap++) {
        int kh = tap / 3, kw = tap - (tap/3)*3;
        uint32_t boff = sb + SM_W + tap*8192 + (whalf*32 + ocb)*128;

#pragma unroll
        for (int ks = 0; ks < 4; ks++) {
            int kcB = ks*2 + khalfB;
            uint32_t bf[8];
#pragma unroll
            for (int i = 0; i < 2; i++) {       // 32 oc = 2 x 16-row blocks
                uint32_t baddr = boff + i*2048 + ((kcB ^ bsw) << 4);
                ldsm4(bf[4*i+0], bf[4*i+1], bf[4*i+2], bf[4*i+3], baddr);
            }
            int kcA = ks*2 + khalfA;
#pragma unroll
            for (int r = 0; r < 4; r++) {
                int pix = (4*wrow + r + kh)*PATCH_W + rA + kw;
                uint32_t aaddr = sb + SM_P + pix*128
                               + ((kcA ^ (pix & 7)) << 4);
                uint32_t a0, a1, a2, a3;
                ldsm4(a0, a1, a2, a3, aaddr);
#pragma unroll
                for (int nt = 0; nt < 4; nt++)
                    mma_f16(acc[r][nt], a0, a1, a2, a3,
                            bf[2*nt], bf[2*nt+1]);
            }
        }
    }

    // ---- epilogue (bias from global; L2-resident) ----
    {
        int r0 = l >> 2;
        int cp = (l & 3) * 2;
#pragma unroll
        for (int r = 0; r < 4; r++) {
            int oh = oh0 + 4*wrow + r;
            size_t pbase = (size_t)bb*OCN*SSZ + (size_t)oh*OHW + ow0;
#pragma unroll
            for (int nt = 0; nt < 4; nt++) {
                int oc = whalf*32 + nt*8 + cp;
                float b0 = __ldg(&g_bias[oc]);
                float b1 = __ldg(&g_bias[oc + 1]);
                float* o0 = out + pbase + (size_t)oc*SSZ;
                float* o1 = o0 + SSZ;
                o0[r0]     = acc[r][nt][0] + b0;
                o1[r0]     = acc[r][nt][1] + b1;
                o0[r0 + 8] = acc[r][nt][2] + b0;
                o1[r0 + 8] = acc[r][nt][3] + b1;
            }
        }
    }
}

// ---------------------------------------------------------------------------
extern "C" void kernel_launch(void* const* d_in, const int* in_sizes, int n_in,
                              void* d_out, int out_size) {
    const float* x   = (const float*)d_in[0];  // [8,32,96,96]
    const float* pos = (const float*)d_in[1];  // [64,32,3,3,3]
    const float* val = (const float*)d_in[2];  // [64,32,3,3,3]
    float* out = (float*)d_out;                // [8,64,96,96]

    cudaFuncSetAttribute(pw_mma_kernel,
                         cudaFuncAttributeMaxDynamicSharedMemorySize,
                         SM_TOTAL);

    prep_w_kernel<<<OCN, 256>>>(pos, val);
    pw_mma_kernel<<<288, 256, SM_TOTAL>>>(x, pos, out);
}

// round 13
// speedup vs baseline: 2.5626x; 1.0770x over previous
#include <cuda_runtime.h>
#include <cuda_fp16.h>
#include <cstdint>

// ---------------------------------------------------------------------------
// Problem constants
// ---------------------------------------------------------------------------
#define BATCH 8
#define CIN   32
#define HH    96
#define WW    96
#define OCN   64
#define OHW   96
#define SSZ   (OHW*OHW)      // 9216
#define KK    (CIN*3*3)      // 288

#define TILE_H 16
#define TILE_W 16
#define PATCH_H 18
#define PATCH_W 18
#define NPIX    (PATCH_H*PATCH_W)    // 324

// Dynamic smem layout (bytes) — 112.5KB; (115200+1024)*2 = 232448 <= 233472
#define SM_W      0                   // resident weights: 9*64 rows x 128B
#define SM_P      73728               // patch fp16: 324 rows x 128B = 41472
#define SM_TOTAL  115200

// Preprocessed weights: [9 tap][64 oc][64 k] fp16 (k = cin | 32+cin)
__device__ __align__(16) __half g_W[9*64*64];
__device__ float g_bias[OCN];

// ---------------------------------------------------------------------------
// Weight prep: grid(64), block(256); tree-reduced bias.
// ---------------------------------------------------------------------------
__global__ __launch_bounds__(256)
void prep_w_kernel(const float* __restrict__ pos,
                   const float* __restrict__ val) {
    __shared__ float red[256];
    const int tid = threadIdx.x;
    const int oc  = blockIdx.x;
    float part = 0.f;
    for (int k = tid; k < KK; k += 256) {
        const float* p = pos + ((size_t)(oc*KK + k))*3;
        const float* v = val + ((size_t)(oc*KK + k))*3;
        float q0 = p[0], q1 = p[1], q2 = p[2];
        float v0 = v[0], v1 = v[1], v2 = v[2];
        float dp0 = q1 - q0, dp1 = q2 - q1;
        float s0 = (dp0 > 0.f) ? (v1 - v0) / dp0 : 0.f;
        float s1 = (dp1 > 0.f) ? (v2 - v1) / dp1 : 0.f;

        int cin = k / 9;
        int tap = k - cin*9;

        size_t rb = ((size_t)tap*64 + oc)*64;
        g_W[rb + cin]      = __float2half(s0);
        g_W[rb + 32 + cin] = __float2half(s1);

        part += v0 - s0*q0 - s1*q1;
    }
    red[tid] = part;
    __syncthreads();
#pragma unroll
    for (int s = 128; s > 0; s >>= 1) {
        if (tid < s) red[tid] += red[tid + s];
        __syncthreads();
    }
    if (tid == 0) g_bias[oc] = red[0];
}

// ---------------------------------------------------------------------------
// MMA / cp.async helpers (baseline sm_80+ PTX)
// ---------------------------------------------------------------------------
__device__ __forceinline__ void ldsm4(uint32_t& r0, uint32_t& r1,
                                      uint32_t& r2, uint32_t& r3,
                                      uint32_t addr) {
    asm volatile("ldmatrix.sync.aligned.m8n8.x4.shared.b16 {%0,%1,%2,%3}, [%4];"
                 : "=r"(r0), "=r"(r1), "=r"(r2), "=r"(r3) : "r"(addr));
}
__device__ __forceinline__ void mma_f16(float* d,
                                        uint32_t a0, uint32_t a1,
                                        uint32_t a2, uint32_t a3,
                                        uint32_t b0, uint32_t b1) {
    asm volatile(
        "mma.sync.aligned.m16n8k16.row.col.f32.f16.f16.f32 "
        "{%0,%1,%2,%3}, {%4,%5,%6,%7}, {%8,%9}, {%0,%1,%2,%3};"
        : "+f"(d[0]), "+f"(d[1]), "+f"(d[2]), "+f"(d[3])
        : "r"(a0), "r"(a1), "r"(a2), "r"(a3), "r"(b0), "r"(b1));
}
__device__ __forceinline__ uint32_t smem_u32(const void* p) {
    uint32_t a;
    asm("{ .reg .u64 t; cvta.to.shared.u64 t, %1; cvt.u32.u64 %0, t; }"
        : "=r"(a) : "l"(p));
    return a;
}
__device__ __forceinline__ void cp_async16(uint32_t dst, const void* src) {
    asm volatile("cp.async.cg.shared.global [%0], [%1], 16;"
                 :: "r"(dst), "l"(src) : "memory");
}
__device__ __forceinline__ void cp_commit() {
    asm volatile("cp.async.commit_group;" ::: "memory");
}
__device__ __forceinline__ void cp_wait0() {
    asm volatile("cp.async.wait_group 0;" ::: "memory");
}
__device__ __forceinline__ uint32_t h2_as_u32(__half2 v) {
    return reinterpret_cast<const uint32_t&>(v);
}

// ---------------------------------------------------------------------------
// Main: grid(288), one 16x16 tile per block; single fp16 A x fp16 W group.
// kw-OUTER tap loop: 6 A-fragments per (kw,ks) are shared by all 3 kh taps
// (pix depends only on r+kh) -> per-warp ldsm cut 216 -> 144.
// ---------------------------------------------------------------------------
__global__ __launch_bounds__(256, 2)
void pw_mma_kernel(const float* __restrict__ x,
                   const float* __restrict__ pos,
                   float* __restrict__ out) {
    extern __shared__ char smem[];
    const uint32_t sb = smem_u32(smem);
    const int tid = threadIdx.x;
    const int l   = tid & 31;
    const int w   = tid >> 5;
    const int whalf = w >> 2;           // oc half (0: oc0-31, 1: oc32-63)
    const int wrow  = w & 3;            // 4 oh rows {4*wrow .. 4*wrow+3}

    // lane constants (validated choreography)
    const int rA     = l & 15;
    const int khalfA = l >> 4;
    const int ocb    = ((l >> 4) & 1)*8 + (l & 7);
    const int khalfB = (l >> 3) & 1;
    const int bsw    = l & 7;

    const int tile = blockIdx.x;               // 0..287
    const int bb   = tile / 36;                // batch 0..7
    const int rem  = tile - bb*36;
    const int oh0  = (rem / 6) * TILE_H;
    const int ow0  = (rem - (rem/6)*6) * TILE_W;

    const float P0f = pos[0], P1f = pos[1], P2f = pos[2];
    const __half2 P0 = __float2half2_rn(P0f);
    const __half2 P1 = __float2half2_rn(P1f);
    const __half2 P2 = __float2half2_rn(P2f);

    // ---- stage ALL weights (cp.async, swizzled) — overlaps patch work ----
    {
        const char* gw = (const char*)g_W;
        for (int idx = tid; idx < 4608; idx += 256) {  // 576 rows x 8 chunks
            int row = idx >> 3, c = idx & 7;
            cp_async16(sb + SM_W + row*128 + ((c ^ (row & 7)) << 4),
                       gw + row*128 + c*16);
        }
        cp_commit();
    }

    // ---- in-kernel patch staging: fp32 x -> clamped fp16, swizzled ----
    {
        const float* xb = x + (size_t)bb * (CIN*HH*WW);
        int offp[2]; int inbp[2];
#pragma unroll
        for (int s = 0; s < 2; s++) {
            int p  = tid + s*256;
            int ph = p / PATCH_W;
            int pw = p - ph*PATCH_W;
            int h  = oh0 - 1 + ph;
            int w2 = ow0 - 1 + pw;
            inbp[s] = (p < NPIX) && ((unsigned)h < HH) && ((unsigned)w2 < WW);
            offp[s] = (inbp[s] ? h*WW + w2 : 0);
        }
#pragma unroll
        for (int jb = 0; jb < 4; jb++) {        // 8 channels per block
#pragma unroll
            for (int s = 0; s < 2; s++) {
                int p = tid + s*256;
                if (p >= NPIX) break;
                uint32_t qa[4], qb[4];
#pragma unroll
                for (int q = 0; q < 4; q++) {
                    int ch = jb*8 + 2*q;
                    float x0 = inbp[s] ? xb[(size_t)ch*HH*WW + offp[s]] : 0.f;
                    float x1 = inbp[s] ? xb[(size_t)(ch+1)*HH*WW + offp[s]]
                                       : 0.f;
                    __half2 hv = __floats2half2_rn(x0, x1);
                    qa[q] = h2_as_u32(__hmin2(__hmax2(hv, P0), P1));
                    qb[q] = h2_as_u32(__hmin2(__hmax2(hv, P1), P2));
                }
                int c0 = jb, c1 = jb + 4;
                *(uint4*)(smem + SM_P + p*128 + ((c0 ^ (p & 7)) << 4)) =
                    make_uint4(qa[0], qa[1], qa[2], qa[3]);
                *(uint4*)(smem + SM_P + p*128 + ((c1 ^ (p & 7)) << 4)) =
                    make_uint4(qb[0], qb[1], qb[2], qb[3]);
            }
        }
    }

    // hoist bias loads: latency hides under the MMA loop
    float bias0[4], bias1[4];
    {
        int cp = (l & 3) * 2;
#pragma unroll
        for (int nt = 0; nt < 4; nt++) {
            int oc = whalf*32 + nt*8 + cp;
            bias0[nt] = __ldg(&g_bias[oc]);
            bias1[nt] = __ldg(&g_bias[oc + 1]);
        }
    }

    cp_wait0();
    __syncthreads();

    // ---- HMMA: kw-outer, A fragments shared across kh ----
    float acc[4][4][4];                 // [row r][nt][frag]
#pragma unroll
    for (int r = 0; r < 4; r++)
#pragma unroll
        for (int nt = 0; nt < 4; nt++)
#pragma unroll
            for (int i = 0; i < 4; i++) acc[r][nt][i] = 0.f;

#pragma unroll
    for (int kw = 0; kw < 3; kw++) {
#pragma unroll
        for (int ks = 0; ks < 4; ks++) {
            // 6 A fragments: i = r + kh in [0,5]
            int kcA = ks*2 + khalfA;
            uint32_t af[6][4];
#pragma unroll
            for (int i = 0; i < 6; i++) {
                int pix = (4*wrow + i)*PATCH_W + rA + kw;
                uint32_t aaddr = sb + SM_P + pix*128
                               + ((kcA ^ (pix & 7)) << 4);
                ldsm4(af[i][0], af[i][1], af[i][2], af[i][3], aaddr);
            }
            int kcB = ks*2 + khalfB;
#pragma unroll
            for (int kh = 0; kh < 3; kh++) {
                int tap = kh*3 + kw;
                uint32_t boff = sb + SM_W + tap*8192
                              + (whalf*32 + ocb)*128;
                uint32_t bf[8];
#pragma unroll
                for (int i = 0; i < 2; i++) {   // 32 oc = 2 x 16-row blocks
                    uint32_t baddr = boff + i*2048 + ((kcB ^ bsw) << 4);
                    ldsm4(bf[4*i+0], bf[4*i+1], bf[4*i+2], bf[4*i+3], baddr);
                }
#pragma unroll
                for (int r = 0; r < 4; r++) {
                    const uint32_t* a = af[r + kh];
#pragma unroll
                    for (int nt = 0; nt < 4; nt++)
                        mma_f16(acc[r][nt], a[0], a[1], a[2], a[3],
                                bf[2*nt], bf[2*nt+1]);
                }
            }
        }
    }

    // ---- epilogue ----
    {
        int r0 = l >> 2;
        int cp = (l & 3) * 2;
#pragma unroll
        for (int r = 0; r < 4; r++) {
            int oh = oh0 + 4*wrow + r;
            size_t pbase = (size_t)bb*OCN*SSZ + (size_t)oh*OHW + ow0;
#pragma unroll
            for (int nt = 0; nt < 4; nt++) {
                int oc = whalf*32 + nt*8 + cp;
                float* o0 = out + pbase + (size_t)oc*SSZ;
                float* o1 = o0 + SSZ;
                o0[r0]     = acc[r][nt][0] + bias0[nt];
                o1[r0]     = acc[r][nt][1] + bias1[nt];
                o0[r0 + 8] = acc[r][nt][2] + bias0[nt];
                o1[r0 + 8] = acc[r][nt][3] + bias1[nt];
            }
        }
    }
}

// ---------------------------------------------------------------------------
extern "C" void kernel_launch(void* const* d_in, const int* in_sizes, int n_in,
                              void* d_out, int out_size) {
    const float* x   = (const float*)d_in[0];  // [8,32,96,96]
    const float* pos = (const float*)d_in[1];  // [64,32,3,3,3]
    const float* val = (const float*)d_in[2];  // [64,32,3,3,3]
    float* out = (float*)d_out;                // [8,64,96,96]

    cudaFuncSetAttribute(pw_mma_kernel,
                         cudaFuncAttributeMaxDynamicSharedMemorySize,
                         SM_TOTAL);

    prep_w_kernel<<<OCN, 256>>>(pos, val);
    pw_mma_kernel<<<288, 256, SM_TOTAL>>>(x, pos, out);
}

// round 14
// speedup vs baseline: 2.5911x; 1.0111x over previous
#include <cuda_runtime.h>
#include <cuda_fp16.h>
#include <cstdint>

// ---------------------------------------------------------------------------
// Problem constants
// ---------------------------------------------------------------------------
#define BATCH 8
#define CIN   32
#define HH    96
#define WW    96
#define OCN   64
#define OHW   96
#define SSZ   (OHW*OHW)      // 9216
#define KK    (CIN*3*3)      // 288

#define TILE_H 16
#define TILE_W 16
#define PATCH_H 18
#define PATCH_W 18
#define NPIX    (PATCH_H*PATCH_W)    // 324

// Dynamic smem layout (bytes) — 112.5KB; (115200+1024)*2 = 232448 <= 233472
#define SM_W      0                   // resident weights: 9*64 rows x 128B
#define SM_P      73728               // patch fp16: 324 rows x 128B = 41472
#define SM_TOTAL  115200

// Preprocessed weights: [9 tap][64 oc][64 k] fp16 (k = cin | 32+cin)
__device__ __align__(16) __half g_W[9*64*64];
__device__ float g_bias[OCN];

// ---------------------------------------------------------------------------
// Weight prep: grid(64), block(256); tree-reduced bias.
// ---------------------------------------------------------------------------
__global__ __launch_bounds__(256)
void prep_w_kernel(const float* __restrict__ pos,
                   const float* __restrict__ val) {
    __shared__ float red[256];
    const int tid = threadIdx.x;
    const int oc  = blockIdx.x;
    float part = 0.f;
    for (int k = tid; k < KK; k += 256) {
        const float* p = pos + ((size_t)(oc*KK + k))*3;
        const float* v = val + ((size_t)(oc*KK + k))*3;
        float q0 = p[0], q1 = p[1], q2 = p[2];
        float v0 = v[0], v1 = v[1], v2 = v[2];
        float dp0 = q1 - q0, dp1 = q2 - q1;
        float s0 = (dp0 > 0.f) ? (v1 - v0) / dp0 : 0.f;
        float s1 = (dp1 > 0.f) ? (v2 - v1) / dp1 : 0.f;

        int cin = k / 9;
        int tap = k - cin*9;

        size_t rb = ((size_t)tap*64 + oc)*64;
        g_W[rb + cin]      = __float2half(s0);
        g_W[rb + 32 + cin] = __float2half(s1);

        part += v0 - s0*q0 - s1*q1;
    }
    red[tid] = part;
    __syncthreads();
#pragma unroll
    for (int s = 128; s > 0; s >>= 1) {
        if (tid < s) red[tid] += red[tid + s];
        __syncthreads();
    }
    if (tid == 0) g_bias[oc] = red[0];
}

// ---------------------------------------------------------------------------
// MMA / cp.async helpers (baseline sm_80+ PTX)
// ---------------------------------------------------------------------------
__device__ __forceinline__ void ldsm4(uint32_t& r0, uint32_t& r1,
                                      uint32_t& r2, uint32_t& r3,
                                      uint32_t addr) {
    asm volatile("ldmatrix.sync.aligned.m8n8.x4.shared.b16 {%0,%1,%2,%3}, [%4];"
                 : "=r"(r0), "=r"(r1), "=r"(r2), "=r"(r3) : "r"(addr));
}
__device__ __forceinline__ void mma_f16(float* d,
                                        uint32_t a0, uint32_t a1,
                                        uint32_t a2, uint32_t a3,
                                        uint32_t b0, uint32_t b1) {
    asm volatile(
        "mma.sync.aligned.m16n8k16.row.col.f32.f16.f16.f32 "
        "{%0,%1,%2,%3}, {%4,%5,%6,%7}, {%8,%9}, {%0,%1,%2,%3};"
        : "+f"(d[0]), "+f"(d[1]), "+f"(d[2]), "+f"(d[3])
        : "r"(a0), "r"(a1), "r"(a2), "r"(a3), "r"(b0), "r"(b1));
}
__device__ __forceinline__ uint32_t smem_u32(const void* p) {
    uint32_t a;
    asm("{ .reg .u64 t; cvta.to.shared.u64 t, %1; cvt.u32.u64 %0, t; }"
        : "=r"(a) : "l"(p));
    return a;
}
__device__ __forceinline__ void cp_async16(uint32_t dst, const void* src) {
    asm volatile("cp.async.cg.shared.global [%0], [%1], 16;"
                 :: "r"(dst), "l"(src) : "memory");
}
__device__ __forceinline__ void cp_commit() {
    asm volatile("cp.async.commit_group;" ::: "memory");
}
__device__ __forceinline__ void cp_wait0() {
    asm volatile("cp.async.wait_group 0;" ::: "memory");
}
__device__ __forceinline__ uint32_t h2_as_u32(__half2 v) {
    return reinterpret_cast<const uint32_t&>(v);
}

// ---- staging helpers: group g covers cin [16g, 16g+16) -> chunks 2g,2g+1
//      (u0) and 2g+4,2g+5 (u1) ----
__device__ __forceinline__ void load16(const float* __restrict__ xb,
                                       int off, int inb, int g, float* xv) {
#pragma unroll
    for (int q = 0; q < 16; q++)
        xv[q] = inb ? xb[(size_t)(g*16 + q)*HH*WW + off] : 0.f;
}
__device__ __forceinline__ void store16(char* smem, int p, int g,
                                        const float* xv,
                                        __half2 P0, __half2 P1, __half2 P2) {
#pragma unroll
    for (int jb2 = 0; jb2 < 2; jb2++) {
        uint32_t qa[4], qb[4];
#pragma unroll
        for (int q = 0; q < 4; q++) {
            __half2 hv = __floats2half2_rn(xv[jb2*8 + 2*q],
                                           xv[jb2*8 + 2*q + 1]);
            qa[q] = h2_as_u32(__hmin2(__hmax2(hv, P0), P1));
            qb[q] = h2_as_u32(__hmin2(__hmax2(hv, P1), P2));
        }
        int c0 = 2*g + jb2, c1 = c0 + 4;
        *(uint4*)(smem + SM_P + p*128 + ((c0 ^ (p & 7)) << 4)) =
            make_uint4(qa[0], qa[1], qa[2], qa[3]);
        *(uint4*)(smem + SM_P + p*128 + ((c1 ^ (p & 7)) << 4)) =
            make_uint4(qb[0], qb[1], qb[2], qb[3]);
    }
}

// MMA half-pass over ks = PART, PART+2 (chunks of channel group PART)
#define MMA_PART(PART)                                                     \
    _Pragma("unroll")                                                      \
    for (int kw = 0; kw < 3; kw++) {                                       \
        _Pragma("unroll")                                                  \
        for (int kk = 0; kk < 2; kk++) {                                   \
            const int ks = (PART) + 2*kk;                                  \
            const int kcA = ks*2 + khalfA;                                 \
            uint32_t af[6][4];                                             \
            _Pragma("unroll")                                              \
            for (int i = 0; i < 6; i++) {                                  \
                int pix = (4*wrow + i)*PATCH_W + rA + kw;                  \
                uint32_t aaddr = sb + SM_P + pix*128                       \
                               + ((kcA ^ (pix & 7)) << 4);                 \
                ldsm4(af[i][0], af[i][1], af[i][2], af[i][3], aaddr);      \
            }                                                              \
            const int kcB = ks*2 + khalfB;                                 \
            _Pragma("unroll")                                              \
            for (int kh = 0; kh < 3; kh++) {                               \
                int tap = kh*3 + kw;                                       \
                uint32_t boff = sb + SM_W + tap*8192                       \
                              + (whalf*32 + ocb)*128;                      \
                uint32_t bf[8];                                            \
                _Pragma("unroll")                                          \
                for (int i = 0; i < 2; i++) {                              \
                    uint32_t baddr = boff + i*2048 + ((kcB ^ bsw) << 4);   \
                    ldsm4(bf[4*i+0], bf[4*i+1], bf[4*i+2], bf[4*i+3],      \
                          baddr);                                          \
                }                                                          \
                _Pragma("unroll")                                          \
                for (int r = 0; r < 4; r++) {                              \
                    const uint32_t* a = af[r + kh];                        \
                    _Pragma("unroll")                                      \
                    for (int nt = 0; nt < 4; nt++)                         \
                        mma_f16(acc[r][nt], a[0], a[1], a[2], a[3],        \
                                bf[2*nt], bf[2*nt+1]);                     \
                }                                                          \
            }                                                              \
        }                                                                  \
    }

// ---------------------------------------------------------------------------
// Main: grid(288), one 16x16 tile per block; single fp16 group; staging
// software-pipelined into the MMA loop (channel-group <-> ks-pair match).
// ---------------------------------------------------------------------------
__global__ __launch_bounds__(256, 2)
void pw_mma_kernel(const float* __restrict__ x,
                   const float* __restrict__ pos,
                   float* __restrict__ out) {
    extern __shared__ char smem[];
    const uint32_t sb = smem_u32(smem);
    const int tid = threadIdx.x;
    const int l   = tid & 31;
    const int w   = tid >> 5;
    const int whalf = w >> 2;           // oc half
    const int wrow  = w & 3;            // 4 oh rows

    // lane constants (validated choreography)
    const int rA     = l & 15;
    const int khalfA = l >> 4;
    const int ocb    = ((l >> 4) & 1)*8 + (l & 7);
    const int khalfB = (l >> 3) & 1;
    const int bsw    = l & 7;

    const int tile = blockIdx.x;               // 0..287
    const int bb   = tile / 36;                // batch 0..7
    const int rem  = tile - bb*36;
    const int oh0  = (rem / 6) * TILE_H;
    const int ow0  = (rem - (rem/6)*6) * TILE_W;

    const float P0f = pos[0], P1f = pos[1], P2f = pos[2];
    const __half2 P0 = __float2half2_rn(P0f);
    const __half2 P1 = __float2half2_rn(P1f);
    const __half2 P2 = __float2half2_rn(P2f);

    // ---- stage ALL weights (cp.async, swizzled) ----
    {
        const char* gw = (const char*)g_W;
        for (int idx = tid; idx < 4608; idx += 256) {  // 576 rows x 8 chunks
            int row = idx >> 3, c = idx & 7;
            cp_async16(sb + SM_W + row*128 + ((c ^ (row & 7)) << 4),
                       gw + row*128 + c*16);
        }
        cp_commit();
    }

    // slot geometry: slot0 = pixel tid (always valid), slot1 = tid+256
    const float* xb = x + (size_t)bb * (CIN*HH*WW);
    int off0, inb0, off1, inb1, p1v;
    {
        int p  = tid;
        int ph = p / PATCH_W, pw = p - ph*PATCH_W;
        int h  = oh0 - 1 + ph, w2 = ow0 - 1 + pw;
        inb0 = ((unsigned)h < HH) && ((unsigned)w2 < WW);
        off0 = inb0 ? h*WW + w2 : 0;
        p  = tid + 256;
        p1v = (p < NPIX);
        ph = p / PATCH_W; pw = p - ph*PATCH_W;
        h  = oh0 - 1 + ph; w2 = ow0 - 1 + pw;
        inb1 = p1v && ((unsigned)h < HH) && ((unsigned)w2 < WW);
        off1 = inb1 ? h*WW + w2 : 0;
    }

    // ---- stage channel group 0 (cin 0-15), both slots ----
    {
        float xv[16];
        load16(xb, off0, inb0, 0, xv);
        store16(smem, tid, 0, xv, P0, P1, P2);
        if (p1v) {
            load16(xb, off1, inb1, 0, xv);
            store16(smem, tid + 256, 0, xv, P0, P1, P2);
        }
    }

    // hoist bias loads
    float bias0[4], bias1[4];
    {
        int cp = (l & 3) * 2;
#pragma unroll
        for (int nt = 0; nt < 4; nt++) {
            int oc = whalf*32 + nt*8 + cp;
            bias0[nt] = __ldg(&g_bias[oc]);
            bias1[nt] = __ldg(&g_bias[oc + 1]);
        }
    }

    cp_wait0();
    __syncthreads();           // weights + group0 visible

    float acc[4][4][4];
#pragma unroll
    for (int r = 0; r < 4; r++)
#pragma unroll
        for (int nt = 0; nt < 4; nt++)
#pragma unroll
            for (int i = 0; i < 4; i++) acc[r][nt][i] = 0.f;

    // ---- prefetch group 1 slot0 x-values, then MMA part 0 overlaps ----
    float xpf[16];
    load16(xb, off0, inb0, 1, xpf);

    MMA_PART(0)                // ks in {0,2}: uses chunks 0,1,4,5

    // ---- finish staging group 1 ----
    store16(smem, tid, 1, xpf, P0, P1, P2);
    if (p1v) {
        float xv[16];
        load16(xb, off1, inb1, 1, xv);
        store16(smem, tid + 256, 1, xv, P0, P1, P2);
    }
    __syncthreads();           // group1 visible

    MMA_PART(1)                // ks in {1,3}: uses chunks 2,3,6,7

    // ---- epilogue ----
    {
        int r0 = l >> 2;
#pragma unroll
        for (int r = 0; r < 4; r++) {
            int oh = oh0 + 4*wrow + r;
            size_t pbase = (size_t)bb*OCN*SSZ + (size_t)oh*OHW + ow0;
#pragma unroll
            for (int nt = 0; nt < 4; nt++) {
                int oc = whalf*32 + nt*8 + (l & 3)*2;
                float* o0 = out + pbase + (size_t)oc*SSZ;
                float* o1 = o0 + SSZ;
                o0[r0]     = acc[r][nt][0] + bias0[nt];
                o1[r0]     = acc[r][nt][1] + bias1[nt];
                o0[r0 + 8] = acc[r][nt][2] + bias0[nt];
                o1[r0 + 8] = acc[r][nt][3] + bias1[nt];
            }
        }
    }
}

// ---------------------------------------------------------------------------
extern "C" void kernel_launch(void* const* d_in, const int* in_sizes, int n_in,
                              void* d_out, int out_size) {
    const float* x   = (const float*)d_in[0];  // [8,32,96,96]
    const float* pos = (const float*)d_in[1];  // [64,32,3,3,3]
    const float* val = (const float*)d_in[2];  // [64,32,3,3,3]
    float* out = (float*)d_out;                // [8,64,96,96]

    cudaFuncSetAttribute(pw_mma_kernel,
                         cudaFuncAttributeMaxDynamicSharedMemorySize,
                         SM_TOTAL);

    prep_w_kernel<<<OCN, 256>>>(pos, val);
    pw_mma_kernel<<<288, 256, SM_TOTAL>>>(x, pos, out);
}